// round 2
// baseline (speedup 1.0000x reference)
#include <cuda_runtime.h>
#include <math.h>

// Problem constants
#define DMODEL 512
#define DFF    2048
#define NHEAD  8
#define DK     64
#define NBLK   4
#define BATCH  2
#define SEQ    2048
#define MROWS  (BATCH*SEQ)   // 4096

// ---------------------------------------------------------------------------
// Scratch (device globals — no allocations allowed)
// ---------------------------------------------------------------------------
__device__ float g_h [MROWS*DMODEL];
__device__ float g_q [MROWS*DMODEL];
__device__ float g_k [MROWS*DMODEL];
__device__ float g_v [MROWS*DMODEL];
__device__ float g_at[MROWS*DMODEL];
__device__ float g_h1[MROWS*DMODEL];
__device__ float g_ff[MROWS*DFF];
__device__ float g_f2[MROWS*DMODEL];

// ---------------------------------------------------------------------------
// Tiled fp32 GEMM: C[M,N] = A[M,K] @ B[K,N] + bias[N], optional ReLU.
// 64x64 tile, BK=32, 256 threads, 4x4 per-thread microtile.
// M % 64 == 0, N % 64 == 0, K % 32 == 0 (true for all shapes here).
// ---------------------------------------------------------------------------
template<bool RELU>
__global__ void gemm_kernel(const float* __restrict__ A,
                            const float* __restrict__ B,
                            const float* __restrict__ bias,
                            float* __restrict__ C,
                            int M, int N, int K) {
    __shared__ float As[32][65];   // As[k][m]
    __shared__ float Bs[32][65];   // Bs[k][n]

    const int tid = threadIdx.x;
    const int tx = tid & 15;
    const int ty = tid >> 4;
    const int row0 = blockIdx.y * 64 + ty * 4;
    const int col0 = blockIdx.x * 64 + tx * 4;

    float acc[4][4];
    #pragma unroll
    for (int i = 0; i < 4; i++)
        #pragma unroll
        for (int j = 0; j < 4; j++) acc[i][j] = 0.f;

    for (int k0 = 0; k0 < K; k0 += 32) {
        // load A tile (64 rows x 32 k), coalesced along K
        #pragma unroll
        for (int i = tid; i < 64 * 32; i += 256) {
            int m  = i >> 5;
            int kk = i & 31;
            As[kk][m] = A[(size_t)(blockIdx.y * 64 + m) * K + k0 + kk];
        }
        // load B tile (32 k x 64 n), coalesced along N
        #pragma unroll
        for (int i = tid; i < 32 * 64; i += 256) {
            int kk = i >> 6;
            int n  = i & 63;
            Bs[kk][n] = B[(size_t)(k0 + kk) * N + blockIdx.x * 64 + n];
        }
        __syncthreads();

        #pragma unroll
        for (int kk = 0; kk < 32; kk++) {
            float a[4], b[4];
            #pragma unroll
            for (int i = 0; i < 4; i++) a[i] = As[kk][ty * 4 + i];
            #pragma unroll
            for (int j = 0; j < 4; j++) b[j] = Bs[kk][tx * 4 + j];
            #pragma unroll
            for (int i = 0; i < 4; i++)
                #pragma unroll
                for (int j = 0; j < 4; j++)
                    acc[i][j] = fmaf(a[i], b[j], acc[i][j]);
        }
        __syncthreads();
    }

    #pragma unroll
    for (int i = 0; i < 4; i++) {
        #pragma unroll
        for (int j = 0; j < 4; j++) {
            float vv = acc[i][j] + bias[col0 + j];
            if (RELU) vv = fmaxf(vv, 0.f);
            C[(size_t)(row0 + i) * N + col0 + j] = vv;
        }
    }
}

// ---------------------------------------------------------------------------
// Flash-attention-style kernel.
// q,k,v,out: [B, S, D] fp32, head h occupies columns [h*64, h*64+64).
// Block = one (batch, head, 64-query tile). 256 threads, 4x4 microtiles.
// Online softmax in registers; replicates the reference quirk:
//   scores exactly equal to 0 are masked to -1e9 (checked per element).
// ---------------------------------------------------------------------------
__global__ void attn_kernel(const float* __restrict__ q,
                            const float* __restrict__ k,
                            const float* __restrict__ v,
                            float* __restrict__ o) {
    extern __shared__ float sm[];
    float (*Qs)[65] = (float(*)[65])(sm);             // Qs[d][r]  (transposed)
    float (*Ks)[65] = (float(*)[65])(sm + 64 * 65);   // Ks[d][c]  (transposed)
    float (*Vs)[65] = (float(*)[65])(sm + 2 * 64 * 65); // Vs[kk][c]
    float (*Ps)[65] = (float(*)[65])(sm + 3 * 64 * 65); // Ps[r][kk]

    const int S = SEQ, D = DMODEL;
    const int qt = blockIdx.x, hh = blockIdx.y, b = blockIdx.z;
    const int tid = threadIdx.x;
    const int tx = tid & 15;
    const int ty = tid >> 4;
    const float scale = 0.125f;   // 1/sqrt(64)

    const float* qbase = q + ((size_t)b * S + qt * 64) * D + hh * 64;
    #pragma unroll
    for (int i = tid; i < 64 * 64; i += 256) {
        int r = i >> 6, c = i & 63;
        Qs[c][r] = qbase[(size_t)r * D + c] * scale;
    }

    float m[4], l[4], O[4][4];
    #pragma unroll
    for (int i = 0; i < 4; i++) {
        m[i] = -1e30f; l[i] = 0.f;
        #pragma unroll
        for (int j = 0; j < 4; j++) O[i][j] = 0.f;
    }
    __syncthreads();

    for (int kt = 0; kt < S / 64; kt++) {
        const float* kbase = k + ((size_t)b * S + kt * 64) * D + hh * 64;
        const float* vbase = v + ((size_t)b * S + kt * 64) * D + hh * 64;
        #pragma unroll
        for (int i = tid; i < 64 * 64; i += 256) {
            int r = i >> 6, c = i & 63;
            Ks[c][r] = kbase[(size_t)r * D + c];
            Vs[r][c] = vbase[(size_t)r * D + c];
        }
        __syncthreads();

        // scores: s[i][j] = sum_d Qs[d][row] * Ks[d][col]   (Q prescaled)
        float s[4][4];
        #pragma unroll
        for (int i = 0; i < 4; i++)
            #pragma unroll
            for (int j = 0; j < 4; j++) s[i][j] = 0.f;

        #pragma unroll 8
        for (int d = 0; d < 64; d++) {
            float a[4], bb[4];
            #pragma unroll
            for (int i = 0; i < 4; i++) a[i] = Qs[d][ty * 4 + i];
            #pragma unroll
            for (int j = 0; j < 4; j++) bb[j] = Ks[d][tx * 4 + j];
            #pragma unroll
            for (int i = 0; i < 4; i++)
                #pragma unroll
                for (int j = 0; j < 4; j++)
                    s[i][j] = fmaf(a[i], bb[j], s[i][j]);
        }

        // quirk + online softmax. Row r=ty*4+i is held by the 16 lanes that
        // share ty (a contiguous 16-lane group within the warp).
        #pragma unroll
        for (int i = 0; i < 4; i++) {
            float tm = -1e30f;
            #pragma unroll
            for (int j = 0; j < 4; j++) {
                if (s[i][j] == 0.0f) s[i][j] = -1e9f;   // reference quirk
                tm = fmaxf(tm, s[i][j]);
            }
            #pragma unroll
            for (int off = 1; off < 16; off <<= 1)
                tm = fmaxf(tm, __shfl_xor_sync(0xffffffffu, tm, off));
            float newm = fmaxf(m[i], tm);
            float corr = expf(m[i] - newm);
            float psum = 0.f;
            #pragma unroll
            for (int j = 0; j < 4; j++) {
                float p = expf(s[i][j] - newm);
                s[i][j] = p;
                psum += p;
            }
            #pragma unroll
            for (int off = 1; off < 16; off <<= 1)
                psum += __shfl_xor_sync(0xffffffffu, psum, off);
            l[i] = l[i] * corr + psum;
            m[i] = newm;
            #pragma unroll
            for (int j = 0; j < 4; j++) O[i][j] *= corr;
        }

        // stage P to shared (columns of O != columns of P per thread)
        #pragma unroll
        for (int i = 0; i < 4; i++)
            #pragma unroll
            for (int j = 0; j < 4; j++)
                Ps[ty * 4 + i][tx * 4 + j] = s[i][j];
        __syncthreads();

        // O += P @ V
        #pragma unroll 8
        for (int kk = 0; kk < 64; kk++) {
            float a[4], bb[4];
            #pragma unroll
            for (int i = 0; i < 4; i++) a[i] = Ps[ty * 4 + i][kk];
            #pragma unroll
            for (int j = 0; j < 4; j++) bb[j] = Vs[kk][tx * 4 + j];
            #pragma unroll
            for (int i = 0; i < 4; i++)
                #pragma unroll
                for (int j = 0; j < 4; j++)
                    O[i][j] = fmaf(a[i], bb[j], O[i][j]);
        }
        __syncthreads();
    }

    float* obase = o + ((size_t)b * S + qt * 64) * D + hh * 64;
    #pragma unroll
    for (int i = 0; i < 4; i++) {
        float inv = 1.f / l[i];
        #pragma unroll
        for (int j = 0; j < 4; j++)
            obase[(size_t)(ty * 4 + i) * D + tx * 4 + j] = O[i][j] * inv;
    }
}

// ---------------------------------------------------------------------------
// Fused residual-add + LayerNorm over D=512. One block per row, 256 threads.
// out = (x - mean)/sqrt(var + eps) * g + beta,  x = a + r
// ---------------------------------------------------------------------------
__global__ void add_ln_kernel(const float* __restrict__ a,
                              const float* __restrict__ r,
                              const float* __restrict__ g,
                              const float* __restrict__ beta,
                              float* __restrict__ out) {
    const int D = DMODEL;
    const int row = blockIdx.x;
    const int tid = threadIdx.x;   // 256 threads, 2 elems each

    float2 xa = ((const float2*)(a + (size_t)row * D))[tid];
    float2 xr = ((const float2*)(r + (size_t)row * D))[tid];
    float x0 = xa.x + xr.x;
    float x1 = xa.y + xr.y;
    float s  = x0 + x1;
    float s2 = x0 * x0 + x1 * x1;

    #pragma unroll
    for (int off = 16; off; off >>= 1) {
        s  += __shfl_xor_sync(0xffffffffu, s,  off);
        s2 += __shfl_xor_sync(0xffffffffu, s2, off);
    }
    __shared__ float sh_s[8], sh_s2[8];
    int w = tid >> 5, lane = tid & 31;
    if (lane == 0) { sh_s[w] = s; sh_s2[w] = s2; }
    __syncthreads();
    if (w == 0) {
        s  = (lane < 8) ? sh_s[lane]  : 0.f;
        s2 = (lane < 8) ? sh_s2[lane] : 0.f;
        #pragma unroll
        for (int off = 4; off; off >>= 1) {
            s  += __shfl_xor_sync(0xffffffffu, s,  off);
            s2 += __shfl_xor_sync(0xffffffffu, s2, off);
        }
        if (lane == 0) { sh_s[0] = s; sh_s2[0] = s2; }
    }
    __syncthreads();

    float mean = sh_s[0]  * (1.f / (float)D);
    float var  = sh_s2[0] * (1.f / (float)D) - mean * mean;
    float rstd = rsqrtf(var + 1e-5f);

    int c0 = tid * 2;
    float y0 = (x0 - mean) * rstd * g[c0]     + beta[c0];
    float y1 = (x1 - mean) * rstd * g[c0 + 1] + beta[c0 + 1];
    ((float2*)(out + (size_t)row * D))[tid] = make_float2(y0, y1);
}

// ---------------------------------------------------------------------------
// Launch
// ---------------------------------------------------------------------------
extern "C" void kernel_launch(void* const* d_in, const int* in_sizes, int n_in,
                              void* d_out, int out_size) {
    const float* x   = (const float*)d_in[0];
    const float* Wq  = (const float*)d_in[1];
    const float* bq  = (const float*)d_in[2];
    const float* Wk  = (const float*)d_in[3];
    const float* bk  = (const float*)d_in[4];
    const float* Wv  = (const float*)d_in[5];
    const float* bv  = (const float*)d_in[6];
    const float* W1  = (const float*)d_in[7];
    const float* b1  = (const float*)d_in[8];
    const float* W2  = (const float*)d_in[9];
    const float* b2  = (const float*)d_in[10];
    const float* g1  = (const float*)d_in[11];
    const float* be1 = (const float*)d_in[12];
    const float* g2  = (const float*)d_in[13];
    const float* be2 = (const float*)d_in[14];
    float* out = (float*)d_out;

    float *h_, *q_, *k_, *v_, *at_, *h1_, *ff_, *f2_;
    cudaGetSymbolAddress((void**)&h_,  g_h);
    cudaGetSymbolAddress((void**)&q_,  g_q);
    cudaGetSymbolAddress((void**)&k_,  g_k);
    cudaGetSymbolAddress((void**)&v_,  g_v);
    cudaGetSymbolAddress((void**)&at_, g_at);
    cudaGetSymbolAddress((void**)&h1_, g_h1);
    cudaGetSymbolAddress((void**)&ff_, g_ff);
    cudaGetSymbolAddress((void**)&f2_, g_f2);

    const size_t attn_smem = 4 * 64 * 65 * sizeof(float);   // 66560 B
    cudaFuncSetAttribute(attn_kernel,
                         cudaFuncAttributeMaxDynamicSharedMemorySize,
                         (int)attn_smem);

    const int M = MROWS;
    dim3 thr(256);
    dim3 grid_qkv(DMODEL / 64, M / 64);   // (8, 64)
    dim3 grid_ff1(DFF    / 64, M / 64);   // (32, 64)
    dim3 grid_ff2(DMODEL / 64, M / 64);   // (8, 64)
    dim3 grid_att(SEQ / 64, NHEAD, BATCH); // (32, 8, 2)

    for (int l = 0; l < NBLK; l++) {
        const float* hin = (l == 0) ? x : h_;

        gemm_kernel<false><<<grid_qkv, thr>>>(hin, Wq + (size_t)l * DMODEL * DMODEL,
                                              bq + (size_t)l * DMODEL, q_, M, DMODEL, DMODEL);
        gemm_kernel<false><<<grid_qkv, thr>>>(hin, Wk + (size_t)l * DMODEL * DMODEL,
                                              bk + (size_t)l * DMODEL, k_, M, DMODEL, DMODEL);
        gemm_kernel<false><<<grid_qkv, thr>>>(hin, Wv + (size_t)l * DMODEL * DMODEL,
                                              bv + (size_t)l * DMODEL, v_, M, DMODEL, DMODEL);

        attn_kernel<<<grid_att, thr, attn_smem>>>(q_, k_, v_, at_);

        add_ln_kernel<<<M, thr>>>(at_, hin, g1 + (size_t)l * DMODEL,
                                  be1 + (size_t)l * DMODEL, h1_);

        gemm_kernel<true ><<<grid_ff1, thr>>>(h1_, W1 + (size_t)l * DMODEL * DFF,
                                              b1 + (size_t)l * DFF, ff_, M, DFF, DMODEL);
        gemm_kernel<false><<<grid_ff2, thr>>>(ff_, W2 + (size_t)l * DFF * DMODEL,
                                              b2 + (size_t)l * DMODEL, f2_, M, DMODEL, DFF);

        float* hout = (l == NBLK - 1) ? out : h_;
        add_ln_kernel<<<M, thr>>>(f2_, h1_, g2 + (size_t)l * DMODEL,
                                  be2 + (size_t)l * DMODEL, hout);
    }
}

// round 3
// speedup vs baseline: 1.0019x; 1.0019x over previous
#include <cuda_runtime.h>
#include <math.h>

// Problem constants
#define DMODEL 512
#define DFF    2048
#define NHEAD  8
#define DK     64
#define NBLK   4
#define BATCH  2
#define SEQ    2048
#define MROWS  (BATCH*SEQ)   // 4096

// ---------------------------------------------------------------------------
// Scratch (device globals — no allocations allowed)
// ---------------------------------------------------------------------------
__device__ float g_h [MROWS*DMODEL];
__device__ float g_q [MROWS*DMODEL];
__device__ float g_k [MROWS*DMODEL];
__device__ float g_v [MROWS*DMODEL];
__device__ float g_at[MROWS*DMODEL];
__device__ float g_h1[MROWS*DMODEL];
__device__ float g_ff[MROWS*DFF];
__device__ float g_f2[MROWS*DMODEL];

// ---------------------------------------------------------------------------
// Tiled fp32 GEMM: C[M,N] = A[M,K] @ B[K,N] + bias[N], optional ReLU.
// 64x64 tile, BK=32, 256 threads, 4x4 per-thread microtile.
// M % 64 == 0, N % 64 == 0, K % 32 == 0 (true for all shapes here).
// ---------------------------------------------------------------------------
template<bool RELU>
__global__ void gemm_kernel(const float* __restrict__ A,
                            const float* __restrict__ B,
                            const float* __restrict__ bias,
                            float* __restrict__ C,
                            int M, int N, int K) {
    __shared__ float As[32][65];   // As[k][m]
    __shared__ float Bs[32][65];   // Bs[k][n]

    const int tid = threadIdx.x;
    const int tx = tid & 15;
    const int ty = tid >> 4;
    const int row0 = blockIdx.y * 64 + ty * 4;
    const int col0 = blockIdx.x * 64 + tx * 4;

    float acc[4][4];
    #pragma unroll
    for (int i = 0; i < 4; i++)
        #pragma unroll
        for (int j = 0; j < 4; j++) acc[i][j] = 0.f;

    for (int k0 = 0; k0 < K; k0 += 32) {
        // load A tile (64 rows x 32 k), coalesced along K
        #pragma unroll
        for (int i = tid; i < 64 * 32; i += 256) {
            int m  = i >> 5;
            int kk = i & 31;
            As[kk][m] = A[(size_t)(blockIdx.y * 64 + m) * K + k0 + kk];
        }
        // load B tile (32 k x 64 n), coalesced along N
        #pragma unroll
        for (int i = tid; i < 32 * 64; i += 256) {
            int kk = i >> 6;
            int n  = i & 63;
            Bs[kk][n] = B[(size_t)(k0 + kk) * N + blockIdx.x * 64 + n];
        }
        __syncthreads();

        #pragma unroll
        for (int kk = 0; kk < 32; kk++) {
            float a[4], b[4];
            #pragma unroll
            for (int i = 0; i < 4; i++) a[i] = As[kk][ty * 4 + i];
            #pragma unroll
            for (int j = 0; j < 4; j++) b[j] = Bs[kk][tx * 4 + j];
            #pragma unroll
            for (int i = 0; i < 4; i++)
                #pragma unroll
                for (int j = 0; j < 4; j++)
                    acc[i][j] = fmaf(a[i], b[j], acc[i][j]);
        }
        __syncthreads();
    }

    #pragma unroll
    for (int i = 0; i < 4; i++) {
        #pragma unroll
        for (int j = 0; j < 4; j++) {
            float vv = acc[i][j] + bias[col0 + j];
            if (RELU) vv = fmaxf(vv, 0.f);
            C[(size_t)(row0 + i) * N + col0 + j] = vv;
        }
    }
}

// ---------------------------------------------------------------------------
// Flash-attention-style kernel.
// q,k,v,out: [B, S, D] fp32, head h occupies columns [h*64, h*64+64).
// Block = one (batch, head, 64-query tile). 256 threads, 4x4 microtiles.
// Online softmax in registers; replicates the reference quirk:
//   scores exactly equal to 0 are masked to -1e9 (checked per element).
// ---------------------------------------------------------------------------
__global__ void attn_kernel(const float* __restrict__ q,
                            const float* __restrict__ k,
                            const float* __restrict__ v,
                            float* __restrict__ o) {
    extern __shared__ float sm[];
    float (*Qs)[65] = (float(*)[65])(sm);             // Qs[d][r]  (transposed)
    float (*Ks)[65] = (float(*)[65])(sm + 64 * 65);   // Ks[d][c]  (transposed)
    float (*Vs)[65] = (float(*)[65])(sm + 2 * 64 * 65); // Vs[kk][c]
    float (*Ps)[65] = (float(*)[65])(sm + 3 * 64 * 65); // Ps[r][kk]

    const int S = SEQ, D = DMODEL;
    const int qt = blockIdx.x, hh = blockIdx.y, b = blockIdx.z;
    const int tid = threadIdx.x;
    const int tx = tid & 15;
    const int ty = tid >> 4;
    const float scale = 0.125f;   // 1/sqrt(64)

    const float* qbase = q + ((size_t)b * S + qt * 64) * D + hh * 64;
    #pragma unroll
    for (int i = tid; i < 64 * 64; i += 256) {
        int r = i >> 6, c = i & 63;
        Qs[c][r] = qbase[(size_t)r * D + c] * scale;
    }

    float m[4], l[4], O[4][4];
    #pragma unroll
    for (int i = 0; i < 4; i++) {
        m[i] = -1e30f; l[i] = 0.f;
        #pragma unroll
        for (int j = 0; j < 4; j++) O[i][j] = 0.f;
    }
    __syncthreads();

    for (int kt = 0; kt < S / 64; kt++) {
        const float* kbase = k + ((size_t)b * S + kt * 64) * D + hh * 64;
        const float* vbase = v + ((size_t)b * S + kt * 64) * D + hh * 64;
        #pragma unroll
        for (int i = tid; i < 64 * 64; i += 256) {
            int r = i >> 6, c = i & 63;
            Ks[c][r] = kbase[(size_t)r * D + c];
            Vs[r][c] = vbase[(size_t)r * D + c];
        }
        __syncthreads();

        // scores: s[i][j] = sum_d Qs[d][row] * Ks[d][col]   (Q prescaled)
        float s[4][4];
        #pragma unroll
        for (int i = 0; i < 4; i++)
            #pragma unroll
            for (int j = 0; j < 4; j++) s[i][j] = 0.f;

        #pragma unroll 8
        for (int d = 0; d < 64; d++) {
            float a[4], bb[4];
            #pragma unroll
            for (int i = 0; i < 4; i++) a[i] = Qs[d][ty * 4 + i];
            #pragma unroll
            for (int j = 0; j < 4; j++) bb[j] = Ks[d][tx * 4 + j];
            #pragma unroll
            for (int i = 0; i < 4; i++)
                #pragma unroll
                for (int j = 0; j < 4; j++)
                    s[i][j] = fmaf(a[i], bb[j], s[i][j]);
        }

        // quirk + online softmax. Row r=ty*4+i is held by the 16 lanes that
        // share ty (a contiguous 16-lane group within the warp).
        #pragma unroll
        for (int i = 0; i < 4; i++) {
            float tm = -1e30f;
            #pragma unroll
            for (int j = 0; j < 4; j++) {
                if (s[i][j] == 0.0f) s[i][j] = -1e9f;   // reference quirk
                tm = fmaxf(tm, s[i][j]);
            }
            #pragma unroll
            for (int off = 1; off < 16; off <<= 1)
                tm = fmaxf(tm, __shfl_xor_sync(0xffffffffu, tm, off));
            float newm = fmaxf(m[i], tm);
            float corr = expf(m[i] - newm);
            float psum = 0.f;
            #pragma unroll
            for (int j = 0; j < 4; j++) {
                float p = expf(s[i][j] - newm);
                s[i][j] = p;
                psum += p;
            }
            #pragma unroll
            for (int off = 1; off < 16; off <<= 1)
                psum += __shfl_xor_sync(0xffffffffu, psum, off);
            l[i] = l[i] * corr + psum;
            m[i] = newm;
            #pragma unroll
            for (int j = 0; j < 4; j++) O[i][j] *= corr;
        }

        // stage P to shared (columns of O != columns of P per thread)
        #pragma unroll
        for (int i = 0; i < 4; i++)
            #pragma unroll
            for (int j = 0; j < 4; j++)
                Ps[ty * 4 + i][tx * 4 + j] = s[i][j];
        __syncthreads();

        // O += P @ V
        #pragma unroll 8
        for (int kk = 0; kk < 64; kk++) {
            float a[4], bb[4];
            #pragma unroll
            for (int i = 0; i < 4; i++) a[i] = Ps[ty * 4 + i][kk];
            #pragma unroll
            for (int j = 0; j < 4; j++) bb[j] = Vs[kk][tx * 4 + j];
            #pragma unroll
            for (int i = 0; i < 4; i++)
                #pragma unroll
                for (int j = 0; j < 4; j++)
                    O[i][j] = fmaf(a[i], bb[j], O[i][j]);
        }
        __syncthreads();
    }

    float* obase = o + ((size_t)b * S + qt * 64) * D + hh * 64;
    #pragma unroll
    for (int i = 0; i < 4; i++) {
        float inv = 1.f / l[i];
        #pragma unroll
        for (int j = 0; j < 4; j++)
            obase[(size_t)(ty * 4 + i) * D + tx * 4 + j] = O[i][j] * inv;
    }
}

// ---------------------------------------------------------------------------
// Fused residual-add + LayerNorm over D=512. One block per row, 256 threads.
// out = (x - mean)/sqrt(var + eps) * g + beta,  x = a + r
// ---------------------------------------------------------------------------
__global__ void add_ln_kernel(const float* __restrict__ a,
                              const float* __restrict__ r,
                              const float* __restrict__ g,
                              const float* __restrict__ beta,
                              float* __restrict__ out) {
    const int D = DMODEL;
    const int row = blockIdx.x;
    const int tid = threadIdx.x;   // 256 threads, 2 elems each

    float2 xa = ((const float2*)(a + (size_t)row * D))[tid];
    float2 xr = ((const float2*)(r + (size_t)row * D))[tid];
    float x0 = xa.x + xr.x;
    float x1 = xa.y + xr.y;
    float s  = x0 + x1;
    float s2 = x0 * x0 + x1 * x1;

    #pragma unroll
    for (int off = 16; off; off >>= 1) {
        s  += __shfl_xor_sync(0xffffffffu, s,  off);
        s2 += __shfl_xor_sync(0xffffffffu, s2, off);
    }
    __shared__ float sh_s[8], sh_s2[8];
    int w = tid >> 5, lane = tid & 31;
    if (lane == 0) { sh_s[w] = s; sh_s2[w] = s2; }
    __syncthreads();
    if (w == 0) {
        s  = (lane < 8) ? sh_s[lane]  : 0.f;
        s2 = (lane < 8) ? sh_s2[lane] : 0.f;
        #pragma unroll
        for (int off = 4; off; off >>= 1) {
            s  += __shfl_xor_sync(0xffffffffu, s,  off);
            s2 += __shfl_xor_sync(0xffffffffu, s2, off);
        }
        if (lane == 0) { sh_s[0] = s; sh_s2[0] = s2; }
    }
    __syncthreads();

    float mean = sh_s[0]  * (1.f / (float)D);
    float var  = sh_s2[0] * (1.f / (float)D) - mean * mean;
    float rstd = rsqrtf(var + 1e-5f);

    int c0 = tid * 2;
    float y0 = (x0 - mean) * rstd * g[c0]     + beta[c0];
    float y1 = (x1 - mean) * rstd * g[c0 + 1] + beta[c0 + 1];
    ((float2*)(out + (size_t)row * D))[tid] = make_float2(y0, y1);
}

// ---------------------------------------------------------------------------
// Launch
// ---------------------------------------------------------------------------
extern "C" void kernel_launch(void* const* d_in, const int* in_sizes, int n_in,
                              void* d_out, int out_size) {
    const float* x   = (const float*)d_in[0];
    const float* Wq  = (const float*)d_in[1];
    const float* bq  = (const float*)d_in[2];
    const float* Wk  = (const float*)d_in[3];
    const float* bk  = (const float*)d_in[4];
    const float* Wv  = (const float*)d_in[5];
    const float* bv  = (const float*)d_in[6];
    const float* W1  = (const float*)d_in[7];
    const float* b1  = (const float*)d_in[8];
    const float* W2  = (const float*)d_in[9];
    const float* b2  = (const float*)d_in[10];
    const float* g1  = (const float*)d_in[11];
    const float* be1 = (const float*)d_in[12];
    const float* g2  = (const float*)d_in[13];
    const float* be2 = (const float*)d_in[14];
    float* out = (float*)d_out;

    float *h_, *q_, *k_, *v_, *at_, *h1_, *ff_, *f2_;
    cudaGetSymbolAddress((void**)&h_,  g_h);
    cudaGetSymbolAddress((void**)&q_,  g_q);
    cudaGetSymbolAddress((void**)&k_,  g_k);
    cudaGetSymbolAddress((void**)&v_,  g_v);
    cudaGetSymbolAddress((void**)&at_, g_at);
    cudaGetSymbolAddress((void**)&h1_, g_h1);
    cudaGetSymbolAddress((void**)&ff_, g_ff);
    cudaGetSymbolAddress((void**)&f2_, g_f2);

    const size_t attn_smem = 4 * 64 * 65 * sizeof(float);   // 66560 B
    cudaFuncSetAttribute(attn_kernel,
                         cudaFuncAttributeMaxDynamicSharedMemorySize,
                         (int)attn_smem);

    const int M = MROWS;
    dim3 thr(256);
    dim3 grid_qkv(DMODEL / 64, M / 64);   // (8, 64)
    dim3 grid_ff1(DFF    / 64, M / 64);   // (32, 64)
    dim3 grid_ff2(DMODEL / 64, M / 64);   // (8, 64)
    dim3 grid_att(SEQ / 64, NHEAD, BATCH); // (32, 8, 2)

    for (int l = 0; l < NBLK; l++) {
        const float* hin = (l == 0) ? x : h_;

        gemm_kernel<false><<<grid_qkv, thr>>>(hin, Wq + (size_t)l * DMODEL * DMODEL,
                                              bq + (size_t)l * DMODEL, q_, M, DMODEL, DMODEL);
        gemm_kernel<false><<<grid_qkv, thr>>>(hin, Wk + (size_t)l * DMODEL * DMODEL,
                                              bk + (size_t)l * DMODEL, k_, M, DMODEL, DMODEL);
        gemm_kernel<false><<<grid_qkv, thr>>>(hin, Wv + (size_t)l * DMODEL * DMODEL,
                                              bv + (size_t)l * DMODEL, v_, M, DMODEL, DMODEL);

        attn_kernel<<<grid_att, thr, attn_smem>>>(q_, k_, v_, at_);

        add_ln_kernel<<<M, thr>>>(at_, hin, g1 + (size_t)l * DMODEL,
                                  be1 + (size_t)l * DMODEL, h1_);

        gemm_kernel<true ><<<grid_ff1, thr>>>(h1_, W1 + (size_t)l * DMODEL * DFF,
                                              b1 + (size_t)l * DFF, ff_, M, DFF, DMODEL);
        gemm_kernel<false><<<grid_ff2, thr>>>(ff_, W2 + (size_t)l * DFF * DMODEL,
                                              b2 + (size_t)l * DMODEL, f2_, M, DMODEL, DFF);

        float* hout = (l == NBLK - 1) ? out : h_;
        add_ln_kernel<<<M, thr>>>(f2_, h1_, g2 + (size_t)l * DMODEL,
                                  be2 + (size_t)l * DMODEL, hout);
    }
}